// round 3
// baseline (speedup 1.0000x reference)
#include <cuda_runtime.h>
#include <stdint.h>

#define NN 100000
#define EE 3200000
#define TT 8
#define FF 64

// ---------------- device scratch (allocation-free) ----------------
__device__ float g_agg[(size_t)NN * 512];     // 204.8 MB: agg[n][t*64+f]
__device__ float g_h1[(size_t)NN * FF];       // 25.6 MB
__device__ int   g_pack[EE];                  // src | (t<<17)
__device__ int   g_edst[EE];                  // dst
__device__ int   g_sedge[EE];                 // packed, sorted by dst
__device__ int   g_cnt[NN];
__device__ int   g_off[NN + 1];
__device__ int   g_cur[NN];
__device__ int   g_mode;                      // 1 = int64 indices, 0 = int32

// f32x2 packed-FMA helpers
#define FMA2(acc, a, b) asm("fma.rn.f32x2 %0, %1, %2, %0;" : "+l"(acc) : "l"(a), "l"(b))
__device__ __forceinline__ unsigned long long pack2(float lo, float hi) {
    unsigned long long r;
    asm("mov.b64 %0, {%1, %2};" : "=l"(r) : "r"(__float_as_uint(lo)), "r"(__float_as_uint(hi)));
    return r;
}
__device__ __forceinline__ float2 unpack2(unsigned long long v) {
    unsigned int lo, hi;
    asm("mov.b64 {%0, %1}, %2;" : "=r"(lo), "=r"(hi) : "l"(v));
    return make_float2(__uint_as_float(lo), __uint_as_float(hi));
}

// ---------------- dtype detection ----------------
__global__ void k_detect(const int* __restrict__ ei) {
    __shared__ int any_nonzero;
    if (threadIdx.x == 0) any_nonzero = 0;
    __syncthreads();
    int v = ei[2 * threadIdx.x + 1];
    if (v != 0) atomicExch(&any_nonzero, 1);
    __syncthreads();
    if (threadIdx.x == 0) g_mode = (any_nonzero == 0) ? 1 : 0;
}

// ---------------- zero the histogram (graph replays!) ----------------
__global__ void k_zero_cnt(void) {
    int i = blockIdx.x * 256 + threadIdx.x;
    if (i < NN) g_cnt[i] = 0;
}

// ---------------- edge prep ----------------
__global__ void k_prep_edges(const void* __restrict__ ei_raw,
                             const void* __restrict__ ti_raw) {
    int e = blockIdx.x * blockDim.x + threadIdx.x;
    if (e >= EE) return;
    int src, dst, t;
    if (g_mode) {
        const long long* ei = (const long long*)ei_raw;
        const long long* ti = (const long long*)ti_raw;
        src = (int)ei[e];
        dst = (int)ei[(size_t)EE + e];
        t   = (int)ti[e];
    } else {
        const int* ei = (const int*)ei_raw;
        const int* ti = (const int*)ti_raw;
        src = ei[e];
        dst = ei[EE + e];
        t   = ti[e];
    }
    g_pack[e] = src | (t << 17);
    g_edst[e] = dst;
}

// ---------------- histogram over dst ----------------
__global__ void k_hist(void) {
    int e = blockIdx.x * 256 + threadIdx.x;
    if (e < EE) atomicAdd(&g_cnt[g_edst[e]], 1);
}

// ---------------- single-block exclusive scan of g_cnt -> g_off/g_cur ------
__global__ void __launch_bounds__(1024) k_scan(void) {
    __shared__ int ps[1024];
    const int CH = 98;               // 1024*98 >= 100000
    int tid = threadIdx.x;
    int base = tid * CH;
    int s = 0;
    for (int i = 0; i < CH; i++) {
        int idx = base + i;
        if (idx < NN) s += g_cnt[idx];
    }
    ps[tid] = s;
    __syncthreads();
    for (int off = 1; off < 1024; off <<= 1) {
        int v = 0;
        if (tid >= off) v = ps[tid - off];
        __syncthreads();
        if (tid >= off) ps[tid] += v;
        __syncthreads();
    }
    int run = (tid == 0) ? 0 : ps[tid - 1];
    for (int i = 0; i < CH; i++) {
        int idx = base + i;
        if (idx < NN) {
            g_off[idx] = run;
            g_cur[idx] = run;
            run += g_cnt[idx];
        }
    }
    if (tid == 1023) g_off[NN] = EE;
}

// ---------------- permute edges into dst-sorted order ----------------
__global__ void k_permute(void) {
    int e = blockIdx.x * 256 + threadIdx.x;
    if (e >= EE) return;
    int d = g_edst[e];
    int pos = atomicAdd(&g_cur[d], 1);
    g_sedge[pos] = g_pack[e];
}

// ---------------- aggregate: agg[d][t*64+f] = sum over edges of in[src][f] --
// one warp per dst; 8 warps per block; accumulators in smem (no atomics).
__global__ void __launch_bounds__(256) k_agg(const float* __restrict__ xin,
                                             float* __restrict__ agg) {
    __shared__ float sagg[8][512];
    int warpid = threadIdx.x >> 5;
    int lane   = threadIdx.x & 31;
    int d = blockIdx.x * 8 + warpid;

#pragma unroll
    for (int i = 0; i < 16; i++) sagg[warpid][lane + i * 32] = 0.f;

    int start = g_off[d];
    int end   = g_off[d + 1];
    const float2* x2 = (const float2*)xin;
    float2* s2 = (float2*)&sagg[warpid][0];      // index: t*32 + lane

    for (int e0 = start; e0 < end; e0 += 32) {
        int ev = 0;
        if (e0 + lane < end) ev = g_sedge[e0 + lane];
        int m = end - e0;
        if (m > 32) m = 32;
        for (int i = 0; i < m; i++) {
            int v   = __shfl_sync(0xffffffffu, ev, i);
            int src = v & 0x1FFFF;
            int t   = v >> 17;
            float2 xv = __ldg(&x2[(size_t)src * 32 + lane]);
            float2 c  = s2[t * 32 + lane];
            c.x += xv.x;
            c.y += xv.y;
            s2[t * 32 + lane] = c;
        }
    }

    float4* a4 = (float4*)(agg + (size_t)d * 512);
    const float4* sg4 = (const float4*)&sagg[warpid][0];
#pragma unroll
    for (int i = 0; i < 4; i++) a4[lane + i * 32] = sg4[lane + i * 32];
}

// ---------------- gemm: out[n] = relu(agg[n] @ W + b)  ([N,512]@[512,64]) ---
// block 128 = 4 warps; 16 nodes per block; warp covers fo4 = warpid*4 + (lane&3),
// node-pairs (ng, ng+8) with ng = lane>>2.
#define XS_STRIDE 516
__global__ void __launch_bounds__(128) k_gemm2(const float* __restrict__ agg,
                                               const float* __restrict__ W,
                                               const float* __restrict__ bias,
                                               float* __restrict__ out) {
    __shared__ float xs[16 * XS_STRIDE];
    int tid = threadIdx.x;
    int nb  = blockIdx.x * 16;

    // stage 16 rows x 512 floats (2048 float4), coalesced
    const float4* ag4 = (const float4*)(agg + (size_t)nb * 512);
#pragma unroll
    for (int k = 0; k < 16; k++) {
        int idx = tid + k * 128;        // 0..2047
        int row = idx >> 7;
        int col = idx & 127;
        float4 v = __ldg(&ag4[idx]);
        *(float4*)&xs[row * XS_STRIDE + col * 4] = v;
    }
    __syncthreads();

    int warpid = tid >> 5, lane = tid & 31;
    int jt  = lane & 3;
    int ng  = lane >> 2;                // 0..7
    int fo4 = warpid * 4 + jt;          // 0..15

    unsigned long long accA0 = 0, accA1 = 0, accB0 = 0, accB1 = 0;
    const float4* W4 = (const float4*)W;     // [512][16]

#pragma unroll 2
    for (int f4 = 0; f4 < 128; f4++) {
        float4 w0 = __ldg(&W4[(f4 * 4 + 0) * 16 + fo4]);
        float4 w1 = __ldg(&W4[(f4 * 4 + 1) * 16 + fo4]);
        float4 w2 = __ldg(&W4[(f4 * 4 + 2) * 16 + fo4]);
        float4 w3 = __ldg(&W4[(f4 * 4 + 3) * 16 + fo4]);
        float4 xa = *(const float4*)&xs[ng * XS_STRIDE + f4 * 4];
        float4 xb = *(const float4*)&xs[(ng + 8) * XS_STRIDE + f4 * 4];

        unsigned long long w0lo = pack2(w0.x, w0.y), w0hi = pack2(w0.z, w0.w);
        unsigned long long w1lo = pack2(w1.x, w1.y), w1hi = pack2(w1.z, w1.w);
        unsigned long long w2lo = pack2(w2.x, w2.y), w2hi = pack2(w2.z, w2.w);
        unsigned long long w3lo = pack2(w3.x, w3.y), w3hi = pack2(w3.z, w3.w);

        unsigned long long xa0 = pack2(xa.x, xa.x), xa1 = pack2(xa.y, xa.y);
        unsigned long long xa2 = pack2(xa.z, xa.z), xa3 = pack2(xa.w, xa.w);
        FMA2(accA0, xa0, w0lo); FMA2(accA1, xa0, w0hi);
        FMA2(accA0, xa1, w1lo); FMA2(accA1, xa1, w1hi);
        FMA2(accA0, xa2, w2lo); FMA2(accA1, xa2, w2hi);
        FMA2(accA0, xa3, w3lo); FMA2(accA1, xa3, w3hi);

        unsigned long long xb0 = pack2(xb.x, xb.x), xb1 = pack2(xb.y, xb.y);
        unsigned long long xb2 = pack2(xb.z, xb.z), xb3 = pack2(xb.w, xb.w);
        FMA2(accB0, xb0, w0lo); FMA2(accB1, xb0, w0hi);
        FMA2(accB0, xb1, w1lo); FMA2(accB1, xb1, w1hi);
        FMA2(accB0, xb2, w2lo); FMA2(accB1, xb2, w2hi);
        FMA2(accB0, xb3, w3lo); FMA2(accB1, xb3, w3hi);
    }

    float4 bv = __ldg(&((const float4*)bias)[fo4]);
    float2 a0 = unpack2(accA0), a1 = unpack2(accA1);
    float2 b0 = unpack2(accB0), b1 = unpack2(accB1);
    float4 ra, rb;
    ra.x = fmaxf(a0.x + bv.x, 0.f); ra.y = fmaxf(a0.y + bv.y, 0.f);
    ra.z = fmaxf(a1.x + bv.z, 0.f); ra.w = fmaxf(a1.y + bv.w, 0.f);
    rb.x = fmaxf(b0.x + bv.x, 0.f); rb.y = fmaxf(b0.y + bv.y, 0.f);
    rb.z = fmaxf(b1.x + bv.z, 0.f); rb.w = fmaxf(b1.y + bv.w, 0.f);
    ((float4*)out)[(size_t)(nb + ng) * 16 + fo4]     = ra;
    ((float4*)out)[(size_t)(nb + ng + 8) * 16 + fo4] = rb;
}

// ---------------- ssl = h2 @ Wssl + bssl ----------------
__global__ void __launch_bounds__(256) k_ssl(const float* __restrict__ h2,
                                             const float* __restrict__ Wssl,
                                             const float* __restrict__ bssl,
                                             float* __restrict__ out) {
    __shared__ float ws[64 * 64];
    __shared__ float hs[4 * 64];
    int tid = threadIdx.x;
    int nb  = blockIdx.x * 4;

    {
        float4* wsv = (float4*)ws;
        const float4* Wv = (const float4*)Wssl;
#pragma unroll
        for (int k = 0; k < 4; k++) wsv[tid + k * 256] = Wv[tid + k * 256];
        hs[tid] = h2[(size_t)nb * 64 + tid];
    }
    __syncthreads();

    int nl = tid >> 6;
    int fo = tid & 63;
    float a = __ldg(&bssl[fo]);
#pragma unroll 8
    for (int fin = 0; fin < 64; ++fin)
        a += hs[nl * 64 + fin] * ws[fin * 64 + fo];
    out[(size_t)(nb + nl) * 64 + fo] = a;
}

// ---------------- launch ----------------
extern "C" void kernel_launch(void* const* d_in, const int* in_sizes, int n_in,
                              void* d_out, int out_size) {
    const float* x    = (const float*)d_in[0];
    const void*  ei   = d_in[1];
    const void*  ti   = d_in[2];
    const float* W1   = (const float*)d_in[3];
    const float* b1   = (const float*)d_in[4];
    const float* W2   = (const float*)d_in[5];
    const float* b2   = (const float*)d_in[6];
    const float* Wssl = (const float*)d_in[7];
    const float* bssl = (const float*)d_in[8];
    float* out_h   = (float*)d_out;
    float* out_ssl = (float*)d_out + (size_t)NN * 64;

    float* dagg; cudaGetSymbolAddress((void**)&dagg, g_agg);
    float* dh1;  cudaGetSymbolAddress((void**)&dh1, g_h1);

    // sort edges by dst (counting sort), once per call
    k_detect<<<1, 256>>>((const int*)ei);
    k_zero_cnt<<<(NN + 255) / 256, 256>>>();
    k_prep_edges<<<EE / 256, 256>>>(ei, ti);
    k_hist<<<EE / 256, 256>>>();
    k_scan<<<1, 1024>>>();
    k_permute<<<EE / 256, 256>>>();

    // layer 1
    k_agg<<<NN / 8, 256>>>(x, dagg);
    k_gemm2<<<NN / 16, 128>>>(dagg, W1, b1, dh1);

    // layer 2
    k_agg<<<NN / 8, 256>>>(dh1, dagg);
    k_gemm2<<<NN / 16, 128>>>(dagg, W2, b2, out_h);

    // ssl head
    k_ssl<<<NN / 4, 256>>>(out_h, Wssl, bssl, out_ssl);
}